// round 1
// baseline (speedup 1.0000x reference)
#include <cuda_runtime.h>
#include <cuda_bf16.h>
#include <math.h>

// Problem shape (fixed by the dataset)
#define BB 16384      // batch
#define KK 50         // items per user
#define HH 64         // embedding dim
#define REGC 0.01f

// Per-block partial reductions (written fresh every launch -> graph-replay safe)
__device__ float g_part_sqerr[BB];
__device__ float g_part_uenorm[BB];
__device__ float g_part_ienorm[BB];

__global__ __launch_bounds__(128, 16)
void mf_main_kernel(const float* __restrict__ user_weight,
                    const float* __restrict__ item_weight,
                    const float* __restrict__ user_bias,
                    const float* __restrict__ item_bias,
                    const float* __restrict__ bias,
                    const float* __restrict__ target,
                    const int*   __restrict__ user,
                    const int*   __restrict__ item,
                    float* __restrict__ out)
{
    __shared__ float s_ue[HH];
    __shared__ float s_warp_sqerr[4];
    __shared__ float s_warp_ienorm[4];

    const int b    = blockIdx.x;
    const int tid  = threadIdx.x;
    const int lane = tid & 31;
    const int wid  = tid >> 5;

    const int   u     = user[b];
    const float ubias = user_bias[u];

    // Load user embedding (+scalar bias) into shared
    if (tid < HH) {
        s_ue[tid] = user_weight[(size_t)u * HH + tid] + ubias;
    }
    __syncthreads();

    const float uex = s_ue[2 * lane];
    const float uey = s_ue[2 * lane + 1];
    const float gb  = bias[0];

    // ||ue|| computed by warp 0
    if (wid == 0) {
        float sq = uex * uex + uey * uey;
        #pragma unroll
        for (int o = 16; o; o >>= 1) sq += __shfl_down_sync(0xffffffffu, sq, o);
        if (lane == 0) g_part_uenorm[b] = sqrtf(sq);
    }

    float sqerr  = 0.f;
    float ienorm = 0.f;

    // Each warp handles items k = wid, wid+4, ...
    for (int k = wid; k < KK; k += 4) {
        const int it = item[(size_t)b * KK + k];          // broadcast load
        const float ibias = item_bias[it];                // broadcast load
        const float2 v = *reinterpret_cast<const float2*>(
            item_weight + (size_t)it * HH + 2 * lane);    // coalesced 256B row
        const float vx = v.x + ibias;
        const float vy = v.y + ibias;

        float dot = uex * vx + uey * vy;
        float sq  = vx * vx + vy * vy;
        #pragma unroll
        for (int o = 16; o; o >>= 1) {
            dot += __shfl_down_sync(0xffffffffu, dot, o);
            sq  += __shfl_down_sync(0xffffffffu, sq,  o);
        }
        if (lane == 0) {
            const float pred = dot + gb;
            out[(size_t)b * KK + k] = pred;
            const float e = pred - target[(size_t)b * KK + k];
            sqerr  += e * e;
            ienorm += sqrtf(sq);
        }
    }

    if (lane == 0) {
        s_warp_sqerr[wid]  = sqerr;
        s_warp_ienorm[wid] = ienorm;
    }
    __syncthreads();

    if (tid == 0) {
        g_part_sqerr[b]  = s_warp_sqerr[0] + s_warp_sqerr[1] +
                           s_warp_sqerr[2] + s_warp_sqerr[3];
        g_part_ienorm[b] = s_warp_ienorm[0] + s_warp_ienorm[1] +
                           s_warp_ienorm[2] + s_warp_ienorm[3];
    }
}

__global__ __launch_bounds__(1024, 1)
void mf_finalize_kernel(float* __restrict__ out)
{
    __shared__ float s0[32], s1[32], s2[32];
    const int tid  = threadIdx.x;
    const int lane = tid & 31;
    const int wid  = tid >> 5;

    float a0 = 0.f, a1 = 0.f, a2 = 0.f;
    for (int i = tid; i < BB; i += 1024) {
        a0 += g_part_sqerr[i];
        a1 += g_part_uenorm[i];
        a2 += g_part_ienorm[i];
    }
    #pragma unroll
    for (int o = 16; o; o >>= 1) {
        a0 += __shfl_down_sync(0xffffffffu, a0, o);
        a1 += __shfl_down_sync(0xffffffffu, a1, o);
        a2 += __shfl_down_sync(0xffffffffu, a2, o);
    }
    if (lane == 0) { s0[wid] = a0; s1[wid] = a1; s2[wid] = a2; }
    __syncthreads();
    if (wid == 0) {
        a0 = s0[lane]; a1 = s1[lane]; a2 = s2[lane];
        #pragma unroll
        for (int o = 16; o; o >>= 1) {
            a0 += __shfl_down_sync(0xffffffffu, a0, o);
            a1 += __shfl_down_sync(0xffffffffu, a1, o);
            a2 += __shfl_down_sync(0xffffffffu, a2, o);
        }
        if (lane == 0) {
            const float inv_bk = 1.0f / (float)((size_t)BB * KK);
            const float mse = a0 * inv_bk;
            const float reg = REGC * (a1 / (float)BB) + REGC * (a2 * inv_bk);
            out[(size_t)BB * KK] = mse + reg;
        }
    }
}

extern "C" void kernel_launch(void* const* d_in, const int* in_sizes, int n_in,
                              void* d_out, int out_size)
{
    const float* user_weight = (const float*)d_in[0];
    const float* item_weight = (const float*)d_in[1];
    const float* user_bias   = (const float*)d_in[2];
    const float* item_bias   = (const float*)d_in[3];
    const float* bias        = (const float*)d_in[4];
    const float* target      = (const float*)d_in[5];
    const int*   user        = (const int*)d_in[6];
    const int*   item        = (const int*)d_in[7];
    float* out = (float*)d_out;

    mf_main_kernel<<<BB, 128>>>(user_weight, item_weight, user_bias, item_bias,
                                bias, target, user, item, out);
    mf_finalize_kernel<<<1, 1024>>>(out);
}